// round 11
// baseline (speedup 1.0000x reference)
#include <cuda_runtime.h>
#include <math.h>
#include <stdint.h>

#define BB 128
#define SS 1024
#define II 256
#define HH 512
#define G3 1536   // 3*H

// ---------------- device scratch ----------------
__device__ float g_xproj[(size_t)BB * SS * G3];   // (B, S, 3H)
__device__ float g_h[2][BB * HH];                 // double-buffered hidden state
__device__ unsigned g_bar[8 * 64];                // per-row-group barrier counters

// ---------------- f32x2 helpers ----------------
__device__ __forceinline__ unsigned long long ffma2(unsigned long long a,
                                                    unsigned long long b,
                                                    unsigned long long c) {
    unsigned long long d;
    asm("fma.rn.f32x2 %0, %1, %2, %3;" : "=l"(d) : "l"(a), "l"(b), "l"(c));
    return d;
}
__device__ __forceinline__ unsigned long long pack2(float x, float y) {
    unsigned long long d;
    asm("mov.b64 %0, {%1, %2};" : "=l"(d) : "f"(x), "f"(y));
    return d;
}
__device__ __forceinline__ float sum2(unsigned long long v) {
    float a, b;
    asm("mov.b64 {%0, %1}, %2;" : "=f"(a), "=f"(b) : "l"(v));
    return a + b;
}

// ---------------- x_proj GEMM: (B*S, I) x (I, 3H) + b_in ----------------
// CTA (0,0) additionally zeroes h0 and ALL barrier counters.
#define XPM 128
#define XPN 64
#define XPK 16

__global__ void __launch_bounds__(256, 2) xproj_kernel(const float* __restrict__ A,
                                                       const float* __restrict__ W,
                                                       const float* __restrict__ bias) {
    if (blockIdx.x == 0 && blockIdx.y == 0) {
        int t = threadIdx.x;
        for (int i = t; i < 8 * 64; i += 256)
            g_bar[i] = 0u;
        for (int i = t; i < BB * HH / 4; i += 256)
            ((float4*)g_h[0])[i] = make_float4(0.f, 0.f, 0.f, 0.f);
    }

    __shared__ float As[XPM * XPK];     // [m][k], stride 16
    __shared__ float Wt[XPN * 18];      // [n][k] transposed, stride 18

    const int m0 = blockIdx.y * XPM;
    const int n0 = blockIdx.x * XPN;
    const int tid = threadIdx.x;
    const int tm = tid >> 4;
    const int tn = tid & 15;
    const int m_base = tm * 8;

    unsigned long long acc[8][4];
#pragma unroll
    for (int i = 0; i < 8; ++i)
#pragma unroll
        for (int j = 0; j < 4; ++j) acc[i][j] = 0ull;

    const int sa_m = tid >> 2;
    const int sa_k = (tid & 3) << 2;
    const int sw_k = tid >> 4;
    const int sw_n = (tid & 15) << 2;

    for (int k0 = 0; k0 < II; k0 += XPK) {
#pragma unroll
        for (int q = 0; q < 2; ++q) {
            int m = sa_m + q * 64;
            *(float4*)&As[m * 16 + sa_k] =
                *(const float4*)(A + (size_t)(m0 + m) * II + k0 + sa_k);
        }
        {
            float4 w = *(const float4*)(W + (size_t)(k0 + sw_k) * G3 + n0 + sw_n);
            Wt[(sw_n + 0) * 18 + sw_k] = w.x;
            Wt[(sw_n + 1) * 18 + sw_k] = w.y;
            Wt[(sw_n + 2) * 18 + sw_k] = w.z;
            Wt[(sw_n + 3) * 18 + sw_k] = w.w;
        }
        __syncthreads();

#pragma unroll
        for (int kk = 0; kk < XPK; kk += 4) {
            ulonglong2 av[8];
#pragma unroll
            for (int i = 0; i < 8; ++i)
                av[i] = *(const ulonglong2*)&As[(m_base + i) * 16 + kk];
#pragma unroll
            for (int j = 0; j < 4; ++j) {
                const float* wp = &Wt[(tn + 16 * j) * 18 + kk];
                unsigned long long w0 = *(const unsigned long long*)(wp);
                unsigned long long w1 = *(const unsigned long long*)(wp + 2);
#pragma unroll
                for (int i = 0; i < 8; ++i) {
                    acc[i][j] = ffma2(av[i].x, w0, acc[i][j]);
                    acc[i][j] = ffma2(av[i].y, w1, acc[i][j]);
                }
            }
        }
        __syncthreads();
    }

    float bb[4];
#pragma unroll
    for (int j = 0; j < 4; ++j) bb[j] = bias[n0 + tn + 16 * j];

#pragma unroll
    for (int i = 0; i < 8; ++i) {
        float* orow = g_xproj + (size_t)(m0 + m_base + i) * G3 + n0 + tn;
#pragma unroll
        for (int j = 0; j < 4; ++j)
            orow[16 * j] = sum2(acc[i][j]) + bb[j];
    }
}

// ---------------- persistent GRU recurrence ----------------
// 128 CTAs = 8 row-tiles (16 batch rows) x 16 col-tiles (32 hidden cols x 3 gates).
// 256 threads = kg(2 k-halves) x rg(4 row groups) x jg(32 cols).
// W_h slice in SMEM as k-quad elements: Ws4[k4][96] of ulonglong2,
//   .x = pack(W[k][c], W[k+1][c]), .y = pack(W[k+2][c], W[k+3][c]).
// Cross-k reduction: kg=1 writes f32 partials into a 12KB buffer overlapping hsm
// (kg=0 pre-reads its h_old values into registers first), kg=0 sums + epilogue.

#define REC_SMEM (96 * 128 * 16 + 16 * HH * 4)   // 196608 + 32768 = 229376 B

__global__ void __launch_bounds__(256, 1) gru_kernel(const float* __restrict__ Wh,
                                                     const float* __restrict__ bias,
                                                     float* __restrict__ out) {
    extern __shared__ float sm[];
    ulonglong2* Ws4 = (ulonglong2*)sm;            // [128][96] 16B elems
    float* hsm = sm + 96 * 128 * 4;               // [16][512] floats (also reduce buf)

    const int tid = threadIdx.x;
    const int ct = blockIdx.x & 15;
    const int rt = blockIdx.x >> 4;
    const int jbase = ct * 32;

    // Stage W_h slice as k-quad packed elements
    for (int i = tid; i < 128 * 96; i += 256) {
        int k4 = i / 96;
        int c = i - k4 * 96;
        int col = (c >> 5) * HH + jbase + (c & 31);
        const float* wp = Wh + (size_t)(4 * k4) * G3 + col;
        ulonglong2 e;
        e.x = pack2(wp[0], wp[G3]);
        e.y = pack2(wp[2 * G3], wp[3 * (size_t)G3]);
        Ws4[i] = e;
    }

    const int kg = tid >> 7;          // 0..1  (k half)
    const int rg = (tid >> 5) & 3;    // 0..3  (row group)
    const int jg = tid & 31;          // 0..31
    const int r0 = rg * 4;
    const int j = jbase + jg;
    const int t128 = tid & 127;       // index within k-half

    float bh[3];
#pragma unroll
    for (int g = 0; g < 3; ++g)
        bh[g] = bias[G3 + g * HH + j];

    __syncthreads();

    const int b0 = rt * 16;
    unsigned* bar = &g_bar[rt * 64];
    const int kbeg = kg * 256;

    for (int s = 0; s < SS; ++s) {
        const float* hin = g_h[s & 1];
        float* hout = g_h[(s + 1) & 1];

        // ---- prefetch x_proj contributions (kg=0 only; consumed in epilogue) ----
        float xv[4][3];
        if (kg == 0) {
#pragma unroll
            for (int ri = 0; ri < 4; ++ri) {
                const float* xp = g_xproj + ((size_t)(b0 + r0 + ri) * SS + s) * G3;
#pragma unroll
                for (int g = 0; g < 3; ++g)
                    xv[ri][g] = __ldg(xp + g * HH + j);
            }
        }

        // ---- stage h tile (16 x 512) from L2 ----
#pragma unroll
        for (int t = 0; t < 8; ++t) {
            int idx = (t * 256 + tid) * 4;
            float4 v = __ldcg((const float4*)(hin + (size_t)b0 * HH + idx));
            *(float4*)(hsm + idx) = v;
        }
        __syncthreads();

        // ---- GEMM over this thread's k half ----
        unsigned long long acc[4][3];
#pragma unroll
        for (int ri = 0; ri < 4; ++ri)
#pragma unroll
            for (int g = 0; g < 3; ++g)
                acc[ri][g] = (kg == 0) ? pack2(bh[g], 0.0f) : pack2(0.0f, 0.0f);

        const float* hr = hsm + r0 * HH;

#pragma unroll 2
        for (int k = kbeg; k < kbeg + 256; k += 4) {
            ulonglong2 hv[4];
#pragma unroll
            for (int ri = 0; ri < 4; ++ri)
                hv[ri] = *(const ulonglong2*)(hr + ri * HH + k);

            const ulonglong2* wrow = Ws4 + (k >> 2) * 96 + jg;
#pragma unroll
            for (int g = 0; g < 3; ++g) {
                ulonglong2 w = wrow[g * 32];
#pragma unroll
                for (int ri = 0; ri < 4; ++ri) {
                    acc[ri][g] = ffma2(hv[ri].x, w.x, acc[ri][g]);
                    acc[ri][g] = ffma2(hv[ri].y, w.y, acc[ri][g]);
                }
            }
        }

        // ---- pre-read h_old before the reduce buffer overwrites hsm ----
        float holds[4];
        if (kg == 0) {
#pragma unroll
            for (int ri = 0; ri < 4; ++ri)
                holds[ri] = hsm[(r0 + ri) * HH + j];
        }
        __syncthreads();

        // ---- kg=1 writes partials into buffer (12KB, overlaps hsm) ----
        if (kg == 1) {
#pragma unroll
            for (int ri = 0; ri < 4; ++ri)
#pragma unroll
                for (int g = 0; g < 3; ++g)
                    hsm[(ri * 3 + g) * 128 + t128] = sum2(acc[ri][g]);
        }
        __syncthreads();

        // ---- kg=0: combine + gates + state update + outputs ----
        if (kg == 0) {
#pragma unroll
            for (int ri = 0; ri < 4; ++ri) {
                int b = b0 + r0 + ri;
                float hrg = sum2(acc[ri][0]) + hsm[(ri * 3 + 0) * 128 + t128];
                float hzg = sum2(acc[ri][1]) + hsm[(ri * 3 + 1) * 128 + t128];
                float hng = sum2(acc[ri][2]) + hsm[(ri * 3 + 2) * 128 + t128];
                float rr = 1.0f / (1.0f + expf(-(xv[ri][0] + hrg)));
                float zz = 1.0f / (1.0f + expf(-(xv[ri][1] + hzg)));
                float nn = tanhf(xv[ri][2] + rr * hng);
                float hnew = (1.0f - zz) * nn + zz * holds[ri];
                out[((size_t)b * SS + s) * HH + j] = hnew;
                hout[(size_t)b * HH + j] = hnew;
                if (s == SS - 1)
                    out[(size_t)BB * SS * HH + (size_t)b * HH + j] = hnew;
            }
        }

        // ---- row-group barrier (16 CTAs) ----
        __threadfence();
        __syncthreads();
        if (tid == 0) {
            atomicAdd(bar, 1u);
            unsigned tgt = 16u * (unsigned)(s + 1);
            while (*(volatile unsigned*)bar < tgt) { }
        }
        __syncthreads();
        __threadfence();
    }
}

// ---------------- launch ----------------
extern "C" void kernel_launch(void* const* d_in, const int* in_sizes, int n_in,
                              void* d_out, int out_size) {
    const float* inputs = (const float*)d_in[0];   // (B, S, I)
    const float* W_in   = (const float*)d_in[1];   // (I, 3H)
    const float* W_h    = (const float*)d_in[2];   // (H, 3H)
    const float* bias   = (const float*)d_in[3];   // (6H,)
    float* out = (float*)d_out;

    dim3 xgrid(G3 / XPN, (BB * SS) / XPM);   // (24, 1024)
    xproj_kernel<<<xgrid, 256>>>(inputs, W_in, bias);

    cudaFuncSetAttribute(gru_kernel, cudaFuncAttributeMaxDynamicSharedMemorySize, REC_SMEM);
    gru_kernel<<<128, 256, REC_SMEM>>>(W_h, bias, out);
}

// round 12
// speedup vs baseline: 1.0006x; 1.0006x over previous
#include <cuda_runtime.h>
#include <math.h>
#include <stdint.h>

#define BB 128
#define SS 1024
#define II 256
#define HH 512
#define G3 1536   // 3*H

// ---------------- device scratch ----------------
__device__ float g_xproj[(size_t)BB * SS * G3];   // (B, S, 3H)
__device__ float g_h[2][BB * HH];                 // double-buffered hidden state
__device__ unsigned g_bar[8 * 64];                // per-row-group barrier counters

// ---------------- f32x2 helpers ----------------
__device__ __forceinline__ unsigned long long ffma2(unsigned long long a,
                                                    unsigned long long b,
                                                    unsigned long long c) {
    unsigned long long d;
    asm("fma.rn.f32x2 %0, %1, %2, %3;" : "=l"(d) : "l"(a), "l"(b), "l"(c));
    return d;
}
__device__ __forceinline__ unsigned long long pack2(float x, float y) {
    unsigned long long d;
    asm("mov.b64 %0, {%1, %2};" : "=l"(d) : "f"(x), "f"(y));
    return d;
}
__device__ __forceinline__ float sum2(unsigned long long v) {
    float a, b;
    asm("mov.b64 {%0, %1}, %2;" : "=f"(a), "=f"(b) : "l"(v));
    return a + b;
}

// ---------------- x_proj GEMM: (B*S, I) x (I, 3H) + b_in ----------------
// CTA (0,0) additionally zeroes h0 and ALL barrier counters.
#define XPM 128
#define XPN 64
#define XPK 16

__global__ void __launch_bounds__(256, 2) xproj_kernel(const float* __restrict__ A,
                                                       const float* __restrict__ W,
                                                       const float* __restrict__ bias) {
    if (blockIdx.x == 0 && blockIdx.y == 0) {
        int t = threadIdx.x;
        for (int i = t; i < 8 * 64; i += 256)
            g_bar[i] = 0u;
        for (int i = t; i < BB * HH / 4; i += 256)
            ((float4*)g_h[0])[i] = make_float4(0.f, 0.f, 0.f, 0.f);
    }

    __shared__ float As[XPM * XPK];     // [m][k], stride 16
    __shared__ float Wt[XPN * 18];      // [n][k] transposed, stride 18

    const int m0 = blockIdx.y * XPM;
    const int n0 = blockIdx.x * XPN;
    const int tid = threadIdx.x;
    const int tm = tid >> 4;
    const int tn = tid & 15;
    const int m_base = tm * 8;

    unsigned long long acc[8][4];
#pragma unroll
    for (int i = 0; i < 8; ++i)
#pragma unroll
        for (int j = 0; j < 4; ++j) acc[i][j] = 0ull;

    const int sa_m = tid >> 2;
    const int sa_k = (tid & 3) << 2;
    const int sw_k = tid >> 4;
    const int sw_n = (tid & 15) << 2;

    for (int k0 = 0; k0 < II; k0 += XPK) {
#pragma unroll
        for (int q = 0; q < 2; ++q) {
            int m = sa_m + q * 64;
            *(float4*)&As[m * 16 + sa_k] =
                *(const float4*)(A + (size_t)(m0 + m) * II + k0 + sa_k);
        }
        {
            float4 w = *(const float4*)(W + (size_t)(k0 + sw_k) * G3 + n0 + sw_n);
            Wt[(sw_n + 0) * 18 + sw_k] = w.x;
            Wt[(sw_n + 1) * 18 + sw_k] = w.y;
            Wt[(sw_n + 2) * 18 + sw_k] = w.z;
            Wt[(sw_n + 3) * 18 + sw_k] = w.w;
        }
        __syncthreads();

#pragma unroll
        for (int kk = 0; kk < XPK; kk += 4) {
            ulonglong2 av[8];
#pragma unroll
            for (int i = 0; i < 8; ++i)
                av[i] = *(const ulonglong2*)&As[(m_base + i) * 16 + kk];
#pragma unroll
            for (int j = 0; j < 4; ++j) {
                const float* wp = &Wt[(tn + 16 * j) * 18 + kk];
                unsigned long long w0 = *(const unsigned long long*)(wp);
                unsigned long long w1 = *(const unsigned long long*)(wp + 2);
#pragma unroll
                for (int i = 0; i < 8; ++i) {
                    acc[i][j] = ffma2(av[i].x, w0, acc[i][j]);
                    acc[i][j] = ffma2(av[i].y, w1, acc[i][j]);
                }
            }
        }
        __syncthreads();
    }

    float bb[4];
#pragma unroll
    for (int j = 0; j < 4; ++j) bb[j] = bias[n0 + tn + 16 * j];

#pragma unroll
    for (int i = 0; i < 8; ++i) {
        float* orow = g_xproj + (size_t)(m0 + m_base + i) * G3 + n0 + tn;
#pragma unroll
        for (int j = 0; j < 4; ++j)
            orow[16 * j] = sum2(acc[i][j]) + bb[j];
    }
}

// ---------------- persistent GRU recurrence ----------------
// 128 CTAs = 8 row-tiles (16 batch rows) x 16 col-tiles (32 hidden cols x 3 gates).
// 256 threads = kg(2 k-halves) x rg(4 row groups) x jg(32 cols).
// W_h slice in SMEM as k-quad elements: Ws4[k4][96] of ulonglong2,
//   .x = pack(W[k][c], W[k+1][c]), .y = pack(W[k+2][c], W[k+3][c]).
// Cross-k reduction: kg=1 writes f32 partials into a 12KB buffer overlapping hsm
// (kg=0 pre-reads its h_old values into registers first), kg=0 sums + epilogue.

#define REC_SMEM (96 * 128 * 16 + 16 * HH * 4)   // 196608 + 32768 = 229376 B

__global__ void __launch_bounds__(256, 1) gru_kernel(const float* __restrict__ Wh,
                                                     const float* __restrict__ bias,
                                                     float* __restrict__ out) {
    extern __shared__ float sm[];
    ulonglong2* Ws4 = (ulonglong2*)sm;            // [128][96] 16B elems
    float* hsm = sm + 96 * 128 * 4;               // [16][512] floats (also reduce buf)

    const int tid = threadIdx.x;
    const int ct = blockIdx.x & 15;
    const int rt = blockIdx.x >> 4;
    const int jbase = ct * 32;

    // Stage W_h slice as k-quad packed elements
    for (int i = tid; i < 128 * 96; i += 256) {
        int k4 = i / 96;
        int c = i - k4 * 96;
        int col = (c >> 5) * HH + jbase + (c & 31);
        const float* wp = Wh + (size_t)(4 * k4) * G3 + col;
        ulonglong2 e;
        e.x = pack2(wp[0], wp[G3]);
        e.y = pack2(wp[2 * G3], wp[3 * (size_t)G3]);
        Ws4[i] = e;
    }

    const int kg = tid >> 7;          // 0..1  (k half)
    const int rg = (tid >> 5) & 3;    // 0..3  (row group)
    const int jg = tid & 31;          // 0..31
    const int r0 = rg * 4;
    const int j = jbase + jg;
    const int t128 = tid & 127;       // index within k-half

    float bh[3];
#pragma unroll
    for (int g = 0; g < 3; ++g)
        bh[g] = bias[G3 + g * HH + j];

    __syncthreads();

    const int b0 = rt * 16;
    unsigned* bar = &g_bar[rt * 64];
    const int kbeg = kg * 256;

    for (int s = 0; s < SS; ++s) {
        const float* hin = g_h[s & 1];
        float* hout = g_h[(s + 1) & 1];

        // ---- prefetch x_proj contributions (kg=0 only; consumed in epilogue) ----
        float xv[4][3];
        if (kg == 0) {
#pragma unroll
            for (int ri = 0; ri < 4; ++ri) {
                const float* xp = g_xproj + ((size_t)(b0 + r0 + ri) * SS + s) * G3;
#pragma unroll
                for (int g = 0; g < 3; ++g)
                    xv[ri][g] = __ldg(xp + g * HH + j);
            }
        }

        // ---- stage h tile (16 x 512) from L2 ----
#pragma unroll
        for (int t = 0; t < 8; ++t) {
            int idx = (t * 256 + tid) * 4;
            float4 v = __ldcg((const float4*)(hin + (size_t)b0 * HH + idx));
            *(float4*)(hsm + idx) = v;
        }
        __syncthreads();

        // ---- GEMM over this thread's k half ----
        unsigned long long acc[4][3];
#pragma unroll
        for (int ri = 0; ri < 4; ++ri)
#pragma unroll
            for (int g = 0; g < 3; ++g)
                acc[ri][g] = (kg == 0) ? pack2(bh[g], 0.0f) : pack2(0.0f, 0.0f);

        const float* hr = hsm + r0 * HH;

#pragma unroll 2
        for (int k = kbeg; k < kbeg + 256; k += 4) {
            ulonglong2 hv[4];
#pragma unroll
            for (int ri = 0; ri < 4; ++ri)
                hv[ri] = *(const ulonglong2*)(hr + ri * HH + k);

            const ulonglong2* wrow = Ws4 + (k >> 2) * 96 + jg;
#pragma unroll
            for (int g = 0; g < 3; ++g) {
                ulonglong2 w = wrow[g * 32];
#pragma unroll
                for (int ri = 0; ri < 4; ++ri) {
                    acc[ri][g] = ffma2(hv[ri].x, w.x, acc[ri][g]);
                    acc[ri][g] = ffma2(hv[ri].y, w.y, acc[ri][g]);
                }
            }
        }

        // ---- pre-read h_old before the reduce buffer overwrites hsm ----
        float holds[4];
        if (kg == 0) {
#pragma unroll
            for (int ri = 0; ri < 4; ++ri)
                holds[ri] = hsm[(r0 + ri) * HH + j];
        }
        __syncthreads();

        // ---- kg=1 writes partials into buffer (12KB, overlaps hsm) ----
        if (kg == 1) {
#pragma unroll
            for (int ri = 0; ri < 4; ++ri)
#pragma unroll
                for (int g = 0; g < 3; ++g)
                    hsm[(ri * 3 + g) * 128 + t128] = sum2(acc[ri][g]);
        }
        __syncthreads();

        // ---- kg=0: combine + gates + state update + outputs ----
        if (kg == 0) {
#pragma unroll
            for (int ri = 0; ri < 4; ++ri) {
                int b = b0 + r0 + ri;
                float hrg = sum2(acc[ri][0]) + hsm[(ri * 3 + 0) * 128 + t128];
                float hzg = sum2(acc[ri][1]) + hsm[(ri * 3 + 1) * 128 + t128];
                float hng = sum2(acc[ri][2]) + hsm[(ri * 3 + 2) * 128 + t128];
                float rr = 1.0f / (1.0f + expf(-(xv[ri][0] + hrg)));
                float zz = 1.0f / (1.0f + expf(-(xv[ri][1] + hzg)));
                float nn = tanhf(xv[ri][2] + rr * hng);
                float hnew = (1.0f - zz) * nn + zz * holds[ri];
                out[((size_t)b * SS + s) * HH + j] = hnew;
                hout[(size_t)b * HH + j] = hnew;
                if (s == SS - 1)
                    out[(size_t)BB * SS * HH + (size_t)b * HH + j] = hnew;
            }
        }

        // ---- row-group barrier (16 CTAs) ----
        __threadfence();
        __syncthreads();
        if (tid == 0) {
            atomicAdd(bar, 1u);
            unsigned tgt = 16u * (unsigned)(s + 1);
            while (*(volatile unsigned*)bar < tgt) { }
        }
        __syncthreads();
        __threadfence();
    }
}

// ---------------- launch ----------------
extern "C" void kernel_launch(void* const* d_in, const int* in_sizes, int n_in,
                              void* d_out, int out_size) {
    const float* inputs = (const float*)d_in[0];   // (B, S, I)
    const float* W_in   = (const float*)d_in[1];   // (I, 3H)
    const float* W_h    = (const float*)d_in[2];   // (H, 3H)
    const float* bias   = (const float*)d_in[3];   // (6H,)
    float* out = (float*)d_out;

    dim3 xgrid(G3 / XPN, (BB * SS) / XPM);   // (24, 1024)
    xproj_kernel<<<xgrid, 256>>>(inputs, W_in, bias);

    cudaFuncSetAttribute(gru_kernel, cudaFuncAttributeMaxDynamicSharedMemorySize, REC_SMEM);
    gru_kernel<<<128, 256, REC_SMEM>>>(W_h, bias, out);
}

// round 13
// speedup vs baseline: 1.0016x; 1.0011x over previous
#include <cuda_runtime.h>
#include <math.h>
#include <stdint.h>

#define BB 128
#define SS 1024
#define II 256
#define HH 512
#define G3 1536   // 3*H

// ---------------- device scratch ----------------
__device__ float g_xproj[(size_t)BB * SS * G3];   // (B, S, 3H)
__device__ float g_h[2][BB * HH];                 // double-buffered hidden state
__device__ unsigned g_bar[8 * 64];                // per-row-group barrier counters

// ---------------- f32x2 helpers ----------------
__device__ __forceinline__ unsigned long long ffma2(unsigned long long a,
                                                    unsigned long long b,
                                                    unsigned long long c) {
    unsigned long long d;
    asm("fma.rn.f32x2 %0, %1, %2, %3;" : "=l"(d) : "l"(a), "l"(b), "l"(c));
    return d;
}
__device__ __forceinline__ unsigned long long pack2(float x, float y) {
    unsigned long long d;
    asm("mov.b64 %0, {%1, %2};" : "=l"(d) : "f"(x), "f"(y));
    return d;
}
__device__ __forceinline__ float sum2(unsigned long long v) {
    float a, b;
    asm("mov.b64 {%0, %1}, %2;" : "=f"(a), "=f"(b) : "l"(v));
    return a + b;
}

// ---------------- x_proj GEMM: (B*S, I) x (I, 3H) + b_in ----------------
// CTA (0,0) additionally zeroes h0 and ALL barrier counters.
#define XPM 128
#define XPN 64
#define XPK 16

__global__ void __launch_bounds__(256, 2) xproj_kernel(const float* __restrict__ A,
                                                       const float* __restrict__ W,
                                                       const float* __restrict__ bias) {
    if (blockIdx.x == 0 && blockIdx.y == 0) {
        int t = threadIdx.x;
        for (int i = t; i < 8 * 64; i += 256)
            g_bar[i] = 0u;
        for (int i = t; i < BB * HH / 4; i += 256)
            ((float4*)g_h[0])[i] = make_float4(0.f, 0.f, 0.f, 0.f);
    }

    __shared__ float As[XPM * XPK];     // [m][k], stride 16
    __shared__ float Wt[XPN * 18];      // [n][k] transposed, stride 18

    const int m0 = blockIdx.y * XPM;
    const int n0 = blockIdx.x * XPN;
    const int tid = threadIdx.x;
    const int tm = tid >> 4;
    const int tn = tid & 15;
    const int m_base = tm * 8;

    unsigned long long acc[8][4];
#pragma unroll
    for (int i = 0; i < 8; ++i)
#pragma unroll
        for (int j = 0; j < 4; ++j) acc[i][j] = 0ull;

    const int sa_m = tid >> 2;
    const int sa_k = (tid & 3) << 2;
    const int sw_k = tid >> 4;
    const int sw_n = (tid & 15) << 2;

    for (int k0 = 0; k0 < II; k0 += XPK) {
#pragma unroll
        for (int q = 0; q < 2; ++q) {
            int m = sa_m + q * 64;
            *(float4*)&As[m * 16 + sa_k] =
                *(const float4*)(A + (size_t)(m0 + m) * II + k0 + sa_k);
        }
        {
            float4 w = *(const float4*)(W + (size_t)(k0 + sw_k) * G3 + n0 + sw_n);
            Wt[(sw_n + 0) * 18 + sw_k] = w.x;
            Wt[(sw_n + 1) * 18 + sw_k] = w.y;
            Wt[(sw_n + 2) * 18 + sw_k] = w.z;
            Wt[(sw_n + 3) * 18 + sw_k] = w.w;
        }
        __syncthreads();

#pragma unroll
        for (int kk = 0; kk < XPK; kk += 4) {
            ulonglong2 av[8];
#pragma unroll
            for (int i = 0; i < 8; ++i)
                av[i] = *(const ulonglong2*)&As[(m_base + i) * 16 + kk];
#pragma unroll
            for (int j = 0; j < 4; ++j) {
                const float* wp = &Wt[(tn + 16 * j) * 18 + kk];
                unsigned long long w0 = *(const unsigned long long*)(wp);
                unsigned long long w1 = *(const unsigned long long*)(wp + 2);
#pragma unroll
                for (int i = 0; i < 8; ++i) {
                    acc[i][j] = ffma2(av[i].x, w0, acc[i][j]);
                    acc[i][j] = ffma2(av[i].y, w1, acc[i][j]);
                }
            }
        }
        __syncthreads();
    }

    float bb[4];
#pragma unroll
    for (int j = 0; j < 4; ++j) bb[j] = bias[n0 + tn + 16 * j];

#pragma unroll
    for (int i = 0; i < 8; ++i) {
        float* orow = g_xproj + (size_t)(m0 + m_base + i) * G3 + n0 + tn;
#pragma unroll
        for (int j = 0; j < 4; ++j)
            orow[16 * j] = sum2(acc[i][j]) + bb[j];
    }
}

// ---------------- persistent GRU recurrence ----------------
// 128 CTAs = 8 row-tiles (16 batch rows) x 16 col-tiles (32 hidden cols x 3 gates).
// 256 threads = kg(2 k-halves) x rg(4 row groups) x jg(32 cols).
// W_h slice in SMEM as k-quad elements: Ws4[k4][96] of ulonglong2,
//   .x = pack(W[k][c], W[k+1][c]), .y = pack(W[k+2][c], W[k+3][c]).
// Cross-k reduction: kg=1 writes f32 partials into a 12KB buffer overlapping hsm
// (kg=0 pre-reads its h_old values into registers first), kg=0 sums + epilogue.

#define REC_SMEM (96 * 128 * 16 + 16 * HH * 4)   // 196608 + 32768 = 229376 B

__global__ void __launch_bounds__(256, 1) gru_kernel(const float* __restrict__ Wh,
                                                     const float* __restrict__ bias,
                                                     float* __restrict__ out) {
    extern __shared__ float sm[];
    ulonglong2* Ws4 = (ulonglong2*)sm;            // [128][96] 16B elems
    float* hsm = sm + 96 * 128 * 4;               // [16][512] floats (also reduce buf)

    const int tid = threadIdx.x;
    const int ct = blockIdx.x & 15;
    const int rt = blockIdx.x >> 4;
    const int jbase = ct * 32;

    // Stage W_h slice as k-quad packed elements
    for (int i = tid; i < 128 * 96; i += 256) {
        int k4 = i / 96;
        int c = i - k4 * 96;
        int col = (c >> 5) * HH + jbase + (c & 31);
        const float* wp = Wh + (size_t)(4 * k4) * G3 + col;
        ulonglong2 e;
        e.x = pack2(wp[0], wp[G3]);
        e.y = pack2(wp[2 * G3], wp[3 * (size_t)G3]);
        Ws4[i] = e;
    }

    const int kg = tid >> 7;          // 0..1  (k half)
    const int rg = (tid >> 5) & 3;    // 0..3  (row group)
    const int jg = tid & 31;          // 0..31
    const int r0 = rg * 4;
    const int j = jbase + jg;
    const int t128 = tid & 127;       // index within k-half

    float bh[3];
#pragma unroll
    for (int g = 0; g < 3; ++g)
        bh[g] = bias[G3 + g * HH + j];

    __syncthreads();

    const int b0 = rt * 16;
    unsigned* bar = &g_bar[rt * 64];
    const int kbeg = kg * 256;

    for (int s = 0; s < SS; ++s) {
        const float* hin = g_h[s & 1];
        float* hout = g_h[(s + 1) & 1];

        // ---- prefetch x_proj contributions (kg=0 only; consumed in epilogue) ----
        float xv[4][3];
        if (kg == 0) {
#pragma unroll
            for (int ri = 0; ri < 4; ++ri) {
                const float* xp = g_xproj + ((size_t)(b0 + r0 + ri) * SS + s) * G3;
#pragma unroll
                for (int g = 0; g < 3; ++g)
                    xv[ri][g] = __ldg(xp + g * HH + j);
            }
        }

        // ---- stage h tile (16 x 512) from L2 ----
#pragma unroll
        for (int t = 0; t < 8; ++t) {
            int idx = (t * 256 + tid) * 4;
            float4 v = __ldcg((const float4*)(hin + (size_t)b0 * HH + idx));
            *(float4*)(hsm + idx) = v;
        }
        __syncthreads();

        // ---- GEMM over this thread's k half ----
        unsigned long long acc[4][3];
#pragma unroll
        for (int ri = 0; ri < 4; ++ri)
#pragma unroll
            for (int g = 0; g < 3; ++g)
                acc[ri][g] = (kg == 0) ? pack2(bh[g], 0.0f) : pack2(0.0f, 0.0f);

        const float* hr = hsm + r0 * HH;

#pragma unroll 2
        for (int k = kbeg; k < kbeg + 256; k += 4) {
            ulonglong2 hv[4];
#pragma unroll
            for (int ri = 0; ri < 4; ++ri)
                hv[ri] = *(const ulonglong2*)(hr + ri * HH + k);

            const ulonglong2* wrow = Ws4 + (k >> 2) * 96 + jg;
#pragma unroll
            for (int g = 0; g < 3; ++g) {
                ulonglong2 w = wrow[g * 32];
#pragma unroll
                for (int ri = 0; ri < 4; ++ri) {
                    acc[ri][g] = ffma2(hv[ri].x, w.x, acc[ri][g]);
                    acc[ri][g] = ffma2(hv[ri].y, w.y, acc[ri][g]);
                }
            }
        }

        // ---- pre-read h_old before the reduce buffer overwrites hsm ----
        float holds[4];
        if (kg == 0) {
#pragma unroll
            for (int ri = 0; ri < 4; ++ri)
                holds[ri] = hsm[(r0 + ri) * HH + j];
        }
        __syncthreads();

        // ---- kg=1 writes partials into buffer (12KB, overlaps hsm) ----
        if (kg == 1) {
#pragma unroll
            for (int ri = 0; ri < 4; ++ri)
#pragma unroll
                for (int g = 0; g < 3; ++g)
                    hsm[(ri * 3 + g) * 128 + t128] = sum2(acc[ri][g]);
        }
        __syncthreads();

        // ---- kg=0: combine + gates + state update + outputs ----
        if (kg == 0) {
#pragma unroll
            for (int ri = 0; ri < 4; ++ri) {
                int b = b0 + r0 + ri;
                float hrg = sum2(acc[ri][0]) + hsm[(ri * 3 + 0) * 128 + t128];
                float hzg = sum2(acc[ri][1]) + hsm[(ri * 3 + 1) * 128 + t128];
                float hng = sum2(acc[ri][2]) + hsm[(ri * 3 + 2) * 128 + t128];
                float rr = 1.0f / (1.0f + expf(-(xv[ri][0] + hrg)));
                float zz = 1.0f / (1.0f + expf(-(xv[ri][1] + hzg)));
                float nn = tanhf(xv[ri][2] + rr * hng);
                float hnew = (1.0f - zz) * nn + zz * holds[ri];
                out[((size_t)b * SS + s) * HH + j] = hnew;
                hout[(size_t)b * HH + j] = hnew;
                if (s == SS - 1)
                    out[(size_t)BB * SS * HH + (size_t)b * HH + j] = hnew;
            }
        }

        // ---- row-group barrier (16 CTAs) ----
        __threadfence();
        __syncthreads();
        if (tid == 0) {
            atomicAdd(bar, 1u);
            unsigned tgt = 16u * (unsigned)(s + 1);
            while (*(volatile unsigned*)bar < tgt) { }
        }
        __syncthreads();
        __threadfence();
    }
}

// ---------------- launch ----------------
extern "C" void kernel_launch(void* const* d_in, const int* in_sizes, int n_in,
                              void* d_out, int out_size) {
    const float* inputs = (const float*)d_in[0];   // (B, S, I)
    const float* W_in   = (const float*)d_in[1];   // (I, 3H)
    const float* W_h    = (const float*)d_in[2];   // (H, 3H)
    const float* bias   = (const float*)d_in[3];   // (6H,)
    float* out = (float*)d_out;

    dim3 xgrid(G3 / XPN, (BB * SS) / XPM);   // (24, 1024)
    xproj_kernel<<<xgrid, 256>>>(inputs, W_in, bias);

    cudaFuncSetAttribute(gru_kernel, cudaFuncAttributeMaxDynamicSharedMemorySize, REC_SMEM);
    gru_kernel<<<128, 256, REC_SMEM>>>(W_h, bias, out);
}